// round 5
// baseline (speedup 1.0000x reference)
#include <cuda_runtime.h>
#include <math.h>

#define HH 512
#define WW 512
#define BB 16
#define IMG (HH*WW)            // 262144 = 1<<18
#define TOT (BB*IMG)           // 4194304
// Tiles: 32 wide x 64 tall -> 16 x 8 per image
#define NTILES 2048
#define MAXR1 24
#define MAXR2 24
#define MAXR3 16
#define NFLAGS (MAXR1+MAXR2+MAXR3)
#define NEG (-INFINITY)

// Scratch (static __device__ arrays: allocation-free)
__device__ float g_m  [TOT];
__device__ float g_m2 [TOT];
__device__ float g_rmx[TOT];
__device__ float g_m3 [TOT];
__device__ unsigned char g_dirty[2][NTILES];
__device__ int   g_chflag[NFLAGS];
__device__ int   g_rflags[2];          // [0]: any Rmax==0, [1]: any Rmax==1
__device__ float g_cc[BB];
__device__ unsigned g_arrive  = 0;
__device__ unsigned g_release = 0;

// ---------------------------------------------------------------------------
// Software grid barrier (all blocks co-resident by construction).
// ---------------------------------------------------------------------------
__device__ __forceinline__ void gbar(unsigned nb, unsigned& target)
{
    __syncthreads();
    if (threadIdx.x == 0) {
        __threadfence();
        unsigned old = atomicInc(&g_arrive, nb - 1);
        if (old == nb - 1) {
            atomicAdd(&g_release, 1);
        } else {
            while (*((volatile unsigned*)&g_release) < target) __nanosleep(32);
        }
        __threadfence();
    }
    target++;
    __syncthreads();
}

// ---------------------------------------------------------------------------
// Block-per-tile chaotic Gauss-Seidel relaxation on a 32x64 tile.
// Thread (tx,ty) owns 8 CONTIGUOUS rows 8*ty..8*ty+7 of column tx.
// Down sweep uses freshly updated cur[k-1] (full 64px vertical reach per
// iteration incl. register up-sweep); in-place smem updates, ONE sync per
// iteration. Races are benign (monotone max-lattice); "no increase in a
// full pass" remains an exact fixpoint test.
// ---------------------------------------------------------------------------
__device__ __forceinline__ bool process_tile(
    float* __restrict__ mk, const float* __restrict__ msk,
    int img, int x0, int y0, float (*sm)[34], int tid)
{
    float* m        = mk  + (size_t)img * IMG;
    const float* ms = msk + (size_t)img * IMG;
    const int ty = tid >> 5, tx = tid & 31;          // ty 0..7, tx 0..31

    // ---- stage interior 64x32 (float4, x0 is 32-aligned): 2 per thread ----
#pragma unroll
    for (int j = 0; j < 2; j++) {
        int i = tid + j * 256;                        // 0..511
        int row = i >> 3, seg = (i & 7) << 2;
        float4 v = __ldcg((const float4*)&m[(y0 + row) * WW + x0 + seg]);
        sm[row + 1][seg + 1] = v.x;
        sm[row + 1][seg + 2] = v.y;
        sm[row + 1][seg + 3] = v.z;
        sm[row + 1][seg + 4] = v.w;
    }
    // ---- halo (196 cells, -inf outside image) ----
    if (tid < 196) {
        int ly, lx, gy, gx;
        if (tid < 34)        { ly = 0;         lx = tid;        gy = y0 - 1;         gx = x0 + tid - 1;  }
        else if (tid < 68)   { ly = 65;        lx = tid - 34;   gy = y0 + 64;        gx = x0 + tid - 35; }
        else if (tid < 132)  { ly = tid - 67;  lx = 0;          gy = y0 + tid - 68;  gx = x0 - 1;        }
        else                 { ly = tid - 131; lx = 33;         gy = y0 + tid - 132; gx = x0 + 32;       }
        float v = NEG;
        if ((unsigned)gx < WW && (unsigned)gy < HH) v = __ldcg(&m[gy * WW + gx]);
        sm[ly][lx] = v;
    }

    float mval[8], cur[8];
#pragma unroll
    for (int k = 0; k < 8; k++)
        mval[k] = __ldg(&ms[(y0 + 8 * ty + k) * WW + x0 + tx]);
    __syncthreads();
#pragma unroll
    for (int k = 0; k < 8; k++)
        cur[k] = sm[8 * ty + k + 1][tx + 1];

    bool any = false;
    for (int it = 0; it < 40; ++it) {
        bool ch = false;
        // down sweep (GS vertical via registers; horizontal/diag via live smem)
#pragma unroll
        for (int k = 0; k < 8; k++) {
            const int r = 8 * ty + k;                 // smem row of up-nbrs
            float up_c = (k > 0) ? cur[k - 1] : sm[r][tx + 1];
            float dn_c = (k < 7) ? cur[k + 1] : sm[r + 2][tx + 1];
            float c = fmaxf(fmaxf(sm[r][tx], up_c), sm[r][tx + 2]);
            c = fmaxf(c, fmaxf(sm[r + 1][tx], sm[r + 1][tx + 2]));
            c = fmaxf(c, fmaxf(fmaxf(sm[r + 2][tx], dn_c), sm[r + 2][tx + 2]));
            float nv = fminf(mval[k], fmaxf(cur[k], c));
            if (nv > cur[k]) { cur[k] = nv; sm[r + 1][tx + 1] = nv; ch = true; }
        }
        // up sweep (register-only vertical back-propagation)
#pragma unroll
        for (int k = 6; k >= 0; k--) {
            float nv = fminf(mval[k], fmaxf(cur[k], cur[k + 1]));
            if (nv > cur[k]) { cur[k] = nv; sm[8 * ty + k + 1][tx + 1] = nv; ch = true; }
        }
        any |= ch;
        if (!__syncthreads_or(ch)) break;
    }

    bool blkany = __syncthreads_or(any);
    if (blkany) {
#pragma unroll
        for (int j = 0; j < 2; j++) {
            int i = tid + j * 256;
            int row = i >> 3, seg = (i & 7) << 2;
            float4 v;
            v.x = sm[row + 1][seg + 1];
            v.y = sm[row + 1][seg + 2];
            v.z = sm[row + 1][seg + 3];
            v.w = sm[row + 1][seg + 4];
            __stcg((float4*)&m[(y0 + row) * WW + x0 + seg], v);
        }
    }
    return blkany;
}

// ---------------------------------------------------------------------------
// Reconstruction: rounds of tile relaxation with dirty-skip + exact early
// exit. Snake ordering across rounds helps backward cross-tile propagation.
// ---------------------------------------------------------------------------
__device__ __forceinline__ void recon(
    float* mk, const float* msk, int maxr, int flagbase,
    unsigned nb, unsigned& target, float (*sm)[34], int tid, int bid)
{
    for (int r = 0; r < maxr; ++r) {
        const int par = r & 1;
        for (int t0 = bid; t0 < NTILES; t0 += (int)nb) {
            const int t = (r & 1) ? (NTILES - 1 - t0) : t0;
            bool need = true;
            if (r > 0) {
                bool mine = false;
                if (tid < 9) {
                    int dy = tid / 3 - 1, dx = tid % 3 - 1;
                    int tyy = (t >> 4) & 7, txx = t & 15;
                    int ny = tyy + dy, nx = txx + dx;
                    if ((unsigned)ny < 8u && (unsigned)nx < 16u)
                        mine = (*(volatile unsigned char*)&g_dirty[par ^ 1][t + dy * 16 + dx]) != 0;
                }
                need = __syncthreads_or(mine);
            }
            bool ch = false;
            if (need) {
                int img = t >> 7, local = t & 127;
                ch = process_tile(mk, msk, img, (local & 15) << 5, (local >> 4) << 6, sm, tid);
            }
            if (tid == 0) {
                *(volatile unsigned char*)&g_dirty[par][t] = ch ? 1 : 0;
                if (ch) *(volatile int*)&g_chflag[flagbase + r] = 1;
            }
            __syncthreads();
        }
        gbar(nb, target);
        if (*(volatile int*)&g_chflag[flagbase + r] == 0) break;  // uniform
    }
}

// ---------------------------------------------------------------------------
// The whole pipeline in one persistent kernel.
// ---------------------------------------------------------------------------
__global__ void __launch_bounds__(256, 5) persistent_kernel(
    const float* __restrict__ x, const float* __restrict__ h,
    const float* __restrict__ u, float* __restrict__ out, int nbi)
{
    __shared__ float sm[66][34];
    __shared__ float red[8];
    const unsigned nb = (unsigned)nbi;
    const int tid = threadIdx.x;
    const int bid = blockIdx.x;
    const int gid = bid * 256 + tid;
    const int nthr = nbi * 256;
    unsigned target = *((volatile unsigned*)&g_release) + 1;

    // ---- P0: g_m = x - h ; reset flags/counters --------------------------
    {
        const float4* x4 = (const float4*)x;
        float4* m4 = (float4*)g_m;
        for (int i4 = gid; i4 < TOT / 4; i4 += nthr) {
            float4 v = __ldg(&x4[i4]);
            float hh = __ldg(&h[i4 >> 16]);
            v.x -= hh; v.y -= hh; v.z -= hh; v.w -= hh;
            __stcg(&m4[i4], v);
        }
        if (bid == 0) {
            if (tid < NFLAGS) __stcg(&g_chflag[tid], 0);
            if (tid < 2)      __stcg(&g_rflags[tid], 0);
            if (tid < BB)     __stcg(&g_cc[tid], 0.0f);
        }
    }
    gbar(nb, target);

    // ---- Rec1: xh = rec(x - h, x) ----------------------------------------
    recon(g_m, x, MAXR1, 0, nb, target, sm, tid, bid);

    // ---- P1: out[16..] = xh ; g_m2 = xh - eps ----------------------------
    {
        const float4* m4 = (const float4*)g_m;
        float4* m24 = (float4*)g_m2;
        float4* o4 = (float4*)(out + 16);
        for (int i4 = gid; i4 < TOT / 4; i4 += nthr) {
            float4 v = __ldcg(&m4[i4]);
            o4[i4] = v;
            v.x -= 1e-5f; v.y -= 1e-5f; v.z -= 1e-5f; v.w -= 1e-5f;
            __stcg(&m24[i4], v);
        }
    }
    gbar(nb, target);

    // ---- Rec2: rec(xh - eps, xh) -----------------------------------------
    recon(g_m2, g_m, MAXR2, MAXR1, nb, target, sm, tid, bid);

    // ---- P2: Rmax = (xh > rec2); M = min(u, Rmax); global min/max flags --
    {
        const float4* m4  = (const float4*)g_m;
        const float4* m24 = (const float4*)g_m2;
        const float4* u4  = (const float4*)u;
        float4* r4 = (float4*)g_rmx;
        float4* m34 = (float4*)g_m3;
        bool a0 = false, a1 = false;
        for (int i4 = gid; i4 < TOT / 4; i4 += nthr) {
            float4 a = __ldcg(&m4[i4]);
            float4 b = __ldcg(&m24[i4]);
            float4 uu = __ldg(&u4[i4]);
            float4 r, m3;
            r.x = (a.x > b.x) ? 1.0f : 0.0f;
            r.y = (a.y > b.y) ? 1.0f : 0.0f;
            r.z = (a.z > b.z) ? 1.0f : 0.0f;
            r.w = (a.w > b.w) ? 1.0f : 0.0f;
            if (r.x == 0.f || r.y == 0.f || r.z == 0.f || r.w == 0.f) a0 = true;
            if (r.x == 1.f || r.y == 1.f || r.z == 1.f || r.w == 1.f) a1 = true;
            m3.x = fminf(uu.x, r.x); m3.y = fminf(uu.y, r.y);
            m3.z = fminf(uu.z, r.z); m3.w = fminf(uu.w, r.w);
            __stcg(&r4[i4], r);
            __stcg(&m34[i4], m3);
        }
        bool b0 = __syncthreads_or(a0);
        bool b1 = __syncthreads_or(a1);
        if (tid == 0) {
            if (b0) *(volatile int*)&g_rflags[0] = 1;
            if (b1) *(volatile int*)&g_rflags[1] = 1;
        }
    }
    gbar(nb, target);

    // ---- Rec3: R = rec(M, Rmax) ------------------------------------------
    recon(g_m3, g_rmx, MAXR3, MAXR1 + MAXR2, nb, target, sm, tid, bid);

    // ---- P3: CC[img] = sum(u == R) ---------------------------------------
    {
        const int ty = tid >> 5, tx = tid & 31;
        for (int t = bid; t < NTILES; t += nbi) {
            int img = t >> 7, local = t & 127;
            int x0 = (local & 15) << 5, y0 = (local >> 4) << 6;
            const float* uu = u + (size_t)img * IMG;
            const float* m3 = g_m3 + (size_t)img * IMG;
            float s = 0.0f;
#pragma unroll
            for (int k = 0; k < 8; k++) {
                int idx = (y0 + 8 * ty + k) * WW + x0 + tx;
                s += (__ldg(&uu[idx]) == __ldcg(&m3[idx])) ? 1.0f : 0.0f;
            }
#pragma unroll
            for (int off = 16; off; off >>= 1)
                s += __shfl_down_sync(0xffffffffu, s, off);
            if ((tid & 31) == 0) red[tid >> 5] = s;
            __syncthreads();
            if (tid == 0) {
                float tot = 0.0f;
#pragma unroll
                for (int w = 0; w < 8; w++) tot += red[w];
                atomicAdd(&g_cc[img], tot);
            }
            __syncthreads();
        }
    }
    gbar(nb, target);

    // ---- P4: CC_ ---------------------------------------------------------
    if (bid == 0 && tid < BB) {
        float maxR = (*(volatile int*)&g_rflags[1]) ? 1.0f : 0.0f;
        float minR = (*(volatile int*)&g_rflags[0]) ? 0.0f : 1.0f;
        float diff = maxR - minR;
        float cc = *(volatile float*)&g_cc[tid];
        out[tid] = fminf(cc, 100.0f * diff * cc);
    }
}

// ---------------------------------------------------------------------------
extern "C" void kernel_launch(void* const* d_in, const int* in_sizes, int n_in,
                              void* d_out, int out_size)
{
    // Identify inputs by size (x and u are 4194304, h is 16; x precedes u)
    const float *x = nullptr, *h = nullptr, *u = nullptr;
    for (int i = 0; i < n_in; i++) {
        if (in_sizes[i] == BB) h = (const float*)d_in[i];
        else if (!x)           x = (const float*)d_in[i];
        else                   u = (const float*)d_in[i];
    }
    float* out = (float*)d_out;

    int dev = 0, sms = 0, occ = 0;
    cudaGetDevice(&dev);
    cudaDeviceGetAttribute(&sms, cudaDevAttrMultiProcessorCount, dev);
    cudaOccupancyMaxActiveBlocksPerMultiprocessor(&occ, persistent_kernel, 256, 0);
    int nb = sms * occ;
    if (nb <= 0) nb = 256;       // conservative fallback, guaranteed resident
    if (nb > 2048) nb = 2048;

    persistent_kernel<<<nb, 256>>>(x, h, u, out, nb);
}